// round 15
// baseline (speedup 1.0000x reference)
#include <cuda_runtime.h>
#include <cuda_fp16.h>
#include <cstdint>

#define QT (16*6*64*49*32)            // 9,633,792 elements per q/k/v tensor

// K-dimension tensors use pair-interleaved layout within each 16-half k-group:
// orig pair q (halves 2q,2q+1) stored at pair ((q&3)<<1)|(q>>2).
__device__ __half g_xh[50176 * 192];  // rolled x, fp16, permuted-k
__device__ __half g_wh[576 * 192];    // wqkv^T [n][k] fp16, permuted-k
__device__ __half g_woh[192 * 192];   // wout^T [n][k] fp16, permuted-k
__device__ __half g_qkvh[3u * QT];    // q|k|v fp16, window layout (q pre-scaled)
__device__ float  g_bias[4 * 4096];   // bias+mask tables [type][i*64+j], pad=-1e9

// ---------------- helpers ----------------
__device__ __forceinline__ void mma16(float* c, const uint32_t* a, const uint32_t* b) {
    asm volatile("mma.sync.aligned.m16n8k16.row.col.f32.f16.f16.f32 "
        "{%0,%1,%2,%3}, {%4,%5,%6,%7}, {%8,%9}, {%0,%1,%2,%3};\n"
        : "+f"(c[0]), "+f"(c[1]), "+f"(c[2]), "+f"(c[3])
        : "r"(a[0]), "r"(a[1]), "r"(a[2]), "r"(a[3]), "r"(b[0]), "r"(b[1]));
}
__device__ __forceinline__ void ldsm4t(uint32_t* r, uint32_t addr) {
    asm volatile("ldmatrix.sync.aligned.m8n8.x4.trans.shared.b16 {%0,%1,%2,%3}, [%4];"
        : "=r"(r[0]), "=r"(r[1]), "=r"(r[2]), "=r"(r[3]) : "r"(addr));
}
__device__ __forceinline__ void cpa16(uint32_t s, const void* g) {
    asm volatile("cp.async.cg.shared.global [%0], [%1], 16;" :: "r"(s), "l"(g));
}
#define CP_COMMIT() asm volatile("cp.async.commit_group;")
#define CP_WAIT2()  asm volatile("cp.async.wait_group 2;")
#define CP_WAIT1()  asm volatile("cp.async.wait_group 1;")
#define CP_WAIT0()  asm volatile("cp.async.wait_group 0;")
__device__ __forceinline__ uint32_t smem_u32(const void* p) {
    uint32_t a;
    asm("{ .reg .u64 t; cvta.to.shared.u64 t, %1; cvt.u32.u64 %0, t; }" : "=r"(a) : "l"(p));
    return a;
}
__device__ __forceinline__ uint32_t h2u(__half2 h) { return *reinterpret_cast<uint32_t*>(&h); }

// ================= merged prep kernel =================
__global__ __launch_bounds__(256) void prep_all(
    const float* __restrict__ x, const float* __restrict__ w,
    const float* __restrict__ wo, const float* __restrict__ pe)
{
    const int blk = blockIdx.x;
    const int tid = threadIdx.x;
    if (blk < 9408) {
        int i = blk * 256 + tid;
        int e = i * 4;
        int t = e / 192, c = e - t * 192;
        int b = t / 3136; int r = t - b * 3136;
        int y = r / 56, xx = r - y * 56;
        int ys = y + 3;  if (ys >= 56) ys -= 56;
        int xs = xx + 3; if (xs >= 56) xs -= 56;
        float4 v = *(const float4*)(x + ((b * 56 + ys) * 56 + xs) * 192 + c);
        int gb = e & ~15;
        int q = (e >> 1) & 7;
        int p0 = ((q & 3) << 1) | (q >> 2);
        int q1 = q + 1;
        int p1 = ((q1 & 3) << 1) | (q1 >> 2);
        *(__half2*)(g_xh + gb + 2 * p0) = __floats2half2_rn(v.x, v.y);
        *(__half2*)(g_xh + gb + 2 * p1) = __floats2half2_rn(v.z, v.w);
    } else if (blk < 9552) {
        int i = (blk - 9408) * 256 + tid;
        int e = i * 4;
        __half* dst;
        float vv[4];
        if (e < 110592) {
            int n = e / 192, k = e - n * 192;
#pragma unroll
            for (int j = 0; j < 4; j++) vv[j] = w[(k + j) * 576 + n];
            dst = g_wh;
        } else {
            int e2 = e - 110592;
            int n = e2 / 192, k = e2 - n * 192;
#pragma unroll
            for (int j = 0; j < 4; j++) vv[j] = wo[(k + j) * 192 + n];
            dst = g_woh - 110592;
        }
        int gb = e & ~15;
        int q = (e >> 1) & 7;
        int p0 = ((q & 3) << 1) | (q >> 2);
        int q1 = q + 1;
        int p1 = ((q1 & 3) << 1) | (q1 >> 2);
        *(__half2*)(dst + gb + 2 * p0) = __floats2half2_rn(vv[0], vv[1]);
        *(__half2*)(dst + gb + 2 * p1) = __floats2half2_rn(vv[2], vv[3]);
    } else {
        int idx = (blk - 9552) * 256 + tid;
        int type = idx >> 12, r = idx & 4095;
        int i = r >> 6, j = r & 63;
        float v = -1e9f;
        if (i < 49 && j < 49) {
            int iy = i / 7, ix = i - iy * 7;
            int jy = j / 7, jx = j - jy * 7;
            v = pe[(jy - iy + 6) * 13 + (jx - ix + 6)];
            if ((type & 2) && ((iy >= 4) != (jy >= 4))) v -= 1e9f;
            if ((type & 1) && ((ix >= 4) != (jx >= 4))) v -= 1e9f;
        }
        g_bias[idx] = v;
    }
}

// ==== QKV GEMM: BM=128, BN=96, BK=64, 128 thr, 2-stage, LDA=80 (R13 exact) ====
#define LDA 80
#define A_ST (128 * LDA)
#define B_ST (96 * LDA)
#define STAGE (A_ST + B_ST)
#define GSMEM (2 * STAGE * 2)        // 71680 B dynamic

__global__ __launch_bounds__(128, 3) void qkv_gemm(void)
{
    extern __shared__ __align__(16) __half sm[];

    const int tid  = threadIdx.x;
    const int warp = tid >> 5, lane = tid & 31;
    const int wm   = warp & 1, wn = warp >> 1;
    const int g    = lane >> 2, tg = lane & 3;
    const int bm   = blockIdx.x * 128;
    const int nb   = blockIdx.y;

    const __half* ap = g_xh + (size_t)(bm + tid) * 192;
    const uint32_t smb = smem_u32(sm);

#define LD_CHUNK(cc, ss) do { \
        uint32_t ad = smb + (uint32_t)((ss) * STAGE + tid * LDA) * 2; \
        const __half* asrc = ap + (cc) * 64; \
        cpa16(ad + 0,  asrc + 0);  cpa16(ad + 16, asrc + 8); \
        cpa16(ad + 32, asrc + 16); cpa16(ad + 48, asrc + 24); \
        cpa16(ad + 64, asrc + 32); cpa16(ad + 80, asrc + 40); \
        cpa16(ad + 96, asrc + 48); cpa16(ad + 112, asrc + 56); \
        uint32_t bd = smb + (uint32_t)((ss) * STAGE + A_ST) * 2; \
        _Pragma("unroll") \
        for (int ii = 0; ii < 6; ii++) { \
            int e = tid + ii * 128; int n = e >> 3, c16 = e & 7; \
            cpa16(bd + (uint32_t)(n * LDA + c16 * 8) * 2, \
                  g_wh + (size_t)(nb * 96 + n) * 192 + (cc) * 64 + c16 * 8); \
        } \
        CP_COMMIT(); } while (0)

    float c[4][6][4] = {};
    LD_CHUNK(0, 0);

#pragma unroll 1
    for (int ch = 0; ch < 3; ch++) {
        const int st = ch & 1;
        __syncthreads();
        if (ch < 2) { LD_CHUNK(ch + 1, st ^ 1); CP_WAIT1(); }
        else        { CP_WAIT0(); }
        __syncthreads();

        const __half* Ab = sm + st * STAGE;
        const __half* Bb = Ab + A_ST;
#pragma unroll
        for (int kk = 0; kk < 64; kk += 16) {
            uint32_t af[4][4], bf[6][2];
#pragma unroll
            for (int mi = 0; mi < 4; mi++) {
                const int rb = wm * 64 + mi * 16 + g;
                uint2 v0 = *(const uint2*)(Ab + rb * LDA + kk + 4 * tg);
                uint2 v1 = *(const uint2*)(Ab + (rb + 8) * LDA + kk + 4 * tg);
                af[mi][0] = v0.x; af[mi][2] = v0.y;
                af[mi][1] = v1.x; af[mi][3] = v1.y;
            }
#pragma unroll
            for (int ni = 0; ni < 6; ni++) {
                uint2 vb = *(const uint2*)(Bb + (wn * 48 + ni * 8 + g) * LDA + kk + 4 * tg);
                bf[ni][0] = vb.x; bf[ni][1] = vb.y;
            }
#pragma unroll
            for (int mi = 0; mi < 4; mi++)
#pragma unroll
                for (int ni = 0; ni < 6; ni++)
                    mma16(c[mi][ni], af[mi], bf[ni]);
        }
    }

    const int t = nb >> 1;
    const float smul = (t == 0) ? 0.17677669529663687f : 1.0f;
    __half* qb = g_qkvh + (size_t)t * QT;
#pragma unroll
    for (int mi = 0; mi < 4; mi++) {
#pragma unroll
        for (int half = 0; half < 2; half++) {
            int r = bm + wm * 64 + mi * 16 + g + half * 8;
            int b = r / 3136; int rr = r - b * 3136;
            int y = rr / 56, xx = rr - y * 56;
            int wv = (y / 7) * 8 + (xx / 7);
            int tk = (y % 7) * 7 + (xx % 7);
            __half* base = qb + b * 602112 + wv * 1568 + tk * 32;
#pragma unroll
            for (int ni = 0; ni < 6; ni++) {
                int cp = nb * 96 + wn * 48 + ni * 8 + tg * 2;
                int cc = cp - t * 192;
                int h = cc >> 5, d = cc & 31;
                *(__half2*)(base + h * 100352 + d) =
                    __floats2half2_rn(c[mi][ni][half * 2] * smul,
                                      c[mi][ni][half * 2 + 1] * smul);
            }
        }
    }
}

// ================= Kernel 2: fused attention + out-proj =================
// Block = (batch, window). 6 heads sequential (QKV double-buffered cp.async),
// O accumulated in smem (permuted-k), then in-block GEMM vs wout + bias + roll.
#define LDQ 40
#define QKV_STG 7680                 // halves per QKV stage (Q|K|V 2560 each)
#define OFF_O 15360                  // halves
#define LDO 208                      // halves per O row (104 words, step 8 mod 32)
#define OFF_B 28672                  // halves
#define LDB 80
#define FSMEM ((28672 + 15360) * 2)  // 88064 bytes

__global__ __launch_bounds__(128, 2) void attn_proj(
    const float* __restrict__ bout, float* __restrict__ out)
{
    extern __shared__ __align__(16) __half fsm[];
    const uint32_t smb = smem_u32(fsm);

    const int tid = threadIdx.x;
    const int w = tid >> 5, lane = tid & 31;
    const int g = lane >> 2, t = lane & 3;
    const int blk = blockIdx.x;
    const int b = blk >> 6, wv = blk & 63;
    const int wy = wv >> 3, wx = wv & 7;
    const int wtype = (wy == 7 ? 2 : 0) | (wx == 7 ? 1 : 0);
    const float* bias = g_bias + wtype * 4096;
    const int hd0 = b * 384 + wv;    // + h*64

    // ---- one-time zero: QKV pad rows 49..63 (both stages), nothing else needed ----
    for (int p = tid; p < 1800; p += 128) {          // 2 stg x 3 tensors x 15 rows x 20 words
        int s = p / 900; int r1 = p - s * 900;
        int tn = r1 / 300; int r2 = r1 - tn * 300;
        int row = 49 + r2 / 20; int wd = r2 % 20;
        *(uint32_t*)(fsm + s * QKV_STG + tn * 2560 + row * LDQ + wd * 2) = 0u;
    }
    // zero O pad rows 49..63
    for (int p = tid; p < 1560; p += 128) {          // 15 rows x 104 words
        int row = 49 + p / 104; int wd = p % 104;
        *(uint32_t*)(fsm + OFF_O + row * LDO + wd * 2) = 0u;
    }

#define LOAD_QKV(hh, ss) do { \
        _Pragma("unroll") \
        for (int ii = 0; ii < 5; ii++) { \
            int e = tid + ii * 128; \
            if (e < 588) { \
                int tn = e / 196; int rem = e - tn * 196; \
                int row = rem >> 2, c16 = rem & 3; \
                cpa16(smb + (uint32_t)((ss) * QKV_STG + tn * 2560 + row * LDQ + c16 * 8) * 2, \
                      g_qkvh + (size_t)tn * QT + (size_t)(hd0 + (hh) * 64) * 1568 + row * 32 + c16 * 8); \
            } \
        } \
        CP_COMMIT(); } while (0)

#define LOAD_B(cc, baseh) do { \
        _Pragma("unroll") \
        for (int ii = 0; ii < 12; ii++) { \
            int e = tid + ii * 128; int n = e >> 3, c16 = e & 7; \
            cpa16(smb + (uint32_t)((baseh) + n * LDB + c16 * 8) * 2, \
                  g_woh + (size_t)n * 192 + (cc) * 64 + c16 * 8); \
        } \
        CP_COMMIT(); } while (0)

    LOAD_QKV(0, 0);

    const int lr = lane & 7, lm = (lane >> 3) & 1, lk = lane >> 4;

    // ================= attention: 6 heads =================
#pragma unroll 1
    for (int h = 0; h < 6; h++) {
        const int st = h & 1;
        if (h > 0) __syncthreads();              // prior head done reading stage st
        if (h < 5) {
            LOAD_QKV(h + 1, st ^ 1);
            if (h == 4) LOAD_B(0, OFF_B);        // prefetch proj chunk 0
        }
        if (h == 4) CP_WAIT2();
        else        CP_WAIT1();
        __syncthreads();

        const __half* Qs = fsm + st * QKV_STG;
        const __half* Ks = Qs + 2560;
        const __half* Vs = Qs + 5120;

        // ---- S = (Q*scale) K^T ; skip padded n=7 ----
        float S[8][4] = {};
        const __half* qrow = Qs + (w * 16 + g) * LDQ;
#pragma unroll
        for (int kk = 0; kk < 32; kk += 16) {
            uint32_t a[4];
            a[0] = *(const uint32_t*)(qrow + kk + 2 * t);
            a[1] = *(const uint32_t*)(qrow + 8 * LDQ + kk + 2 * t);
            a[2] = *(const uint32_t*)(qrow + kk + 8 + 2 * t);
            a[3] = *(const uint32_t*)(qrow + 8 * LDQ + kk + 8 + 2 * t);
#pragma unroll
            for (int n = 0; n < 7; n++) {
                uint32_t bb[2];
                const __half* kb = Ks + (n * 8 + g) * LDQ + kk + 2 * t;
                bb[0] = *(const uint32_t*)(kb);
                bb[1] = *(const uint32_t*)(kb + 8);
                mma16(S[n], a, bb);
            }
        }

        // ---- bias + softmax (real j only) ----
#pragma unroll
        for (int rw = 0; rw < 2; rw++) {
            int i = w * 16 + g + rw * 8;
            const float* brow = bias + i * 64 + 2 * t;
            float mx = -1e30f;
#pragma unroll
            for (int n = 0; n < 6; n++) {
                float2 bb = *(const float2*)(brow + n * 8);
                float v0 = S[n][rw * 2]     + bb.x;
                float v1 = S[n][rw * 2 + 1] + bb.y;
                S[n][rw * 2]     = v0;
                S[n][rw * 2 + 1] = v1;
                mx = fmaxf(mx, fmaxf(v0, v1));
            }
            float v6 = -1e30f;
            if (t == 0) {
                v6 = S[6][rw * 2] + brow[48];
                mx = fmaxf(mx, v6);
            }
            mx = fmaxf(mx, __shfl_xor_sync(0xffffffffu, mx, 1));
            mx = fmaxf(mx, __shfl_xor_sync(0xffffffffu, mx, 2));
            float sm = 0.f;
#pragma unroll
            for (int n = 0; n < 6; n++) {
#pragma unroll
                for (int e = 0; e < 2; e++) {
                    float ex = __expf(S[n][rw * 2 + e] - mx);
                    S[n][rw * 2 + e] = ex;
                    sm += ex;
                }
            }
            if (t == 0) {
                float e6 = __expf(v6 - mx);
                S[6][rw * 2] = e6;
                sm += e6;
            } else {
                S[6][rw * 2] = 0.f;
            }
            S[6][rw * 2 + 1] = 0.f;
            S[7][rw * 2] = 0.f;
            S[7][rw * 2 + 1] = 0.f;
            sm += __shfl_xor_sync(0xffffffffu, sm, 1);
            sm += __shfl_xor_sync(0xffffffffu, sm, 2);
            float inv = 1.f / sm;
#pragma unroll
            for (int n = 0; n < 6; n++) {
                S[n][rw * 2 + 0] *= inv;
                S[n][rw * 2 + 1] *= inv;
            }
            S[6][rw * 2] *= inv;
        }

        // ---- repack P ----
        uint32_t Pa[4][4];
#pragma unroll
        for (int c2 = 0; c2 < 4; c2++) {
            Pa[c2][0] = h2u(__floats2half2_rn(S[2 * c2][0],     S[2 * c2][1]));
            Pa[c2][1] = h2u(__floats2half2_rn(S[2 * c2][2],     S[2 * c2][3]));
            Pa[c2][2] = h2u(__floats2half2_rn(S[2 * c2 + 1][0], S[2 * c2 + 1][1]));
            Pa[c2][3] = h2u(__floats2half2_rn(S[2 * c2 + 1][2], S[2 * c2 + 1][3]));
        }

        // ---- O = P V ----
        const uint32_t vs_b = smb + (uint32_t)(st * QKV_STG + 5120) * 2;
        float O[4][4] = {};
#pragma unroll
        for (int c2 = 0; c2 < 4; c2++) {
#pragma unroll
            for (int nh = 0; nh < 2; nh++) {
                uint32_t r[4];
                ldsm4t(r, vs_b + (uint32_t)((c2 * 16 + lr + lm * 8) * LDQ + nh * 16 + lk * 8) * 2);
                uint32_t b0[2] = { r[0], r[1] };
                uint32_t b1[2] = { r[2], r[3] };
                mma16(O[nh * 2],     Pa[c2], b0);
                mma16(O[nh * 2 + 1], Pa[c2], b1);
            }
        }

        // ---- store O to smem, permuted-k, column base 32h ----
        __half* og = fsm + OFF_O;
#pragma unroll
        for (int rw = 0; rw < 2; rw++) {
            int i = w * 16 + g + rw * 8;
            if (i < 49) {
#pragma unroll
                for (int nt = 0; nt < 4; nt++) {
                    int hh = nt * 8 + 2 * t;
                    int b16 = hh & 16;
                    int q = (hh >> 1) & 7;
                    int pp = ((q & 3) << 1) | (q >> 2);
                    *(__half2*)(og + i * LDO + 32 * h + b16 + 2 * pp) =
                        __floats2half2_rn(O[nt][rw * 2], O[nt][rw * 2 + 1]);
                }
            }
        }
    }

    // ================= proj: out[49x192] = O[64x192] x woh^T + bias, inverse roll =================
    const int wm = w & 1, wn = w >> 1;            // 2 x 2 warps: M=32, N=96 per warp
    const uint32_t bbase[2] = { OFF_B, 0 };       // chunk parity 0 -> B region, 1 -> QKV region

    __syncthreads();                               // O complete; QKV region dead
    LOAD_B(1, bbase[1]);

    float c[2][12][4] = {};

#pragma unroll 1
    for (int ch = 0; ch < 3; ch++) {
        if (ch == 0)      CP_WAIT1();
        else if (ch == 1) CP_WAIT1();
        else              CP_WAIT0();
        __syncthreads();

        const __half* Ab = fsm + OFF_O;
        const __half* Bb = fsm + bbase[ch & 1];
#pragma unroll
        for (int kk = 0; kk < 64; kk += 16) {
            uint32_t af[2][4], bf[12][2];
#pragma unroll
            for (int mi = 0; mi < 2; mi++) {
                const int rb = wm * 32 + mi * 16 + g;
                uint2 v0 = *(const uint2*)(Ab + rb * LDO + ch * 64 + kk + 4 * t);
                uint2 v1 = *(const uint2*)(Ab + (rb + 8) * LDO + ch * 64 + kk + 4 * t);
                af[mi][0] = v0.x; af[mi][2] = v0.y;
                af[mi][1] = v1.x; af[mi][3] = v1.y;
            }
#pragma unroll
            for (int ni = 0; ni < 12; ni++) {
                uint2 vb = *(const uint2*)(Bb + (wn * 96 + ni * 8 + g) * LDB + kk + 4 * t);
                bf[ni][0] = vb.x; bf[ni][1] = vb.y;
            }
#pragma unroll
            for (int mi = 0; mi < 2; mi++)
#pragma unroll
                for (int ni = 0; ni < 12; ni++)
                    mma16(c[mi][ni], af[mi], bf[ni]);
        }

        if (ch == 0) {
            __syncthreads();                       // all warps done with B region
            LOAD_B(2, bbase[0]);
        }
    }

    // epilogue: bias + inverse roll
#pragma unroll
    for (int mi = 0; mi < 2; mi++) {
#pragma unroll
        for (int half = 0; half < 2; half++) {
            int r = wm * 32 + mi * 16 + g + half * 8;
            if (r < 49) {
                int iy = r / 7, ix = r - iy * 7;
                int yo = wy * 7 + iy + 3; if (yo >= 56) yo -= 56;
                int xo = wx * 7 + ix + 3; if (xo >= 56) xo -= 56;
                float* op = out + ((b * 56 + yo) * 56 + xo) * 192;
#pragma unroll
                for (int ni = 0; ni < 12; ni++) {
                    int cp = wn * 96 + ni * 8 + t * 2;
                    float2 bb = *(const float2*)(bout + cp);
                    float2 v = make_float2(c[mi][ni][half * 2] + bb.x,
                                           c[mi][ni][half * 2 + 1] + bb.y);
                    *(float2*)(op + cp) = v;
                }
            }
        }
    }
}

// ================= launch =================
extern "C" void kernel_launch(void* const* d_in, const int* in_sizes, int n_in,
                              void* d_out, int out_size)
{
    const float* x    = (const float*)d_in[0];
    const float* wqkv = (const float*)d_in[1];
    const float* pe   = (const float*)d_in[2];
    const float* wout = (const float*)d_in[3];
    const float* bout = (const float*)d_in[4];
    float* out = (float*)d_out;

    static int configured = 0;
    if (!configured) {
        cudaFuncSetAttribute(qkv_gemm, cudaFuncAttributeMaxDynamicSharedMemorySize, GSMEM);
        cudaFuncSetAttribute(attn_proj, cudaFuncAttributeMaxDynamicSharedMemorySize, FSMEM);
        configured = 1;
    }

    prep_all<<<9616, 256>>>(x, wqkv, wout, pe);

    dim3 g1(392, 6);
    qkv_gemm<<<g1, 128, GSMEM>>>();

    attn_proj<<<16 * 64, 128, FSMEM>>>(bout, out);
}

// round 16
// speedup vs baseline: 1.0620x; 1.0620x over previous
#include <cuda_runtime.h>
#include <cuda_fp16.h>
#include <cstdint>

#define QT (16*6*64*49*32)            // 9,633,792 elements per q/k/v tensor

// K-dimension tensors use pair-interleaved layout within each 16-half k-group:
// orig pair q (halves 2q,2q+1) stored at pair ((q&3)<<1)|(q>>2).
__device__ __half g_xh[50176 * 192];  // rolled x, fp16, permuted-k
__device__ __half g_wh[576 * 192];    // wqkv^T [n][k] fp16, permuted-k
__device__ __half g_woh[192 * 192];   // wout^T [n][k] fp16, permuted-k
__device__ __half g_qkvh[3u * QT];    // q|k|v fp16, window layout (q pre-scaled)
__device__ __half g_atth[QT];         // attention out fp16, window layout, permuted-k
__device__ float  g_bias[4 * 4096];   // bias+mask tables [type][i*64+j], pad=-1e9

// ---------------- helpers ----------------
__device__ __forceinline__ void mma16(float* c, const uint32_t* a, const uint32_t* b) {
    asm volatile("mma.sync.aligned.m16n8k16.row.col.f32.f16.f16.f32 "
        "{%0,%1,%2,%3}, {%4,%5,%6,%7}, {%8,%9}, {%0,%1,%2,%3};\n"
        : "+f"(c[0]), "+f"(c[1]), "+f"(c[2]), "+f"(c[3])
        : "r"(a[0]), "r"(a[1]), "r"(a[2]), "r"(a[3]), "r"(b[0]), "r"(b[1]));
}
__device__ __forceinline__ void ldsm4t(uint32_t* r, uint32_t addr) {
    asm volatile("ldmatrix.sync.aligned.m8n8.x4.trans.shared.b16 {%0,%1,%2,%3}, [%4];"
        : "=r"(r[0]), "=r"(r[1]), "=r"(r[2]), "=r"(r[3]) : "r"(addr));
}
__device__ __forceinline__ void cpa16(uint32_t s, const void* g) {
    asm volatile("cp.async.cg.shared.global [%0], [%1], 16;" :: "r"(s), "l"(g));
}
#define CP_COMMIT() asm volatile("cp.async.commit_group;")
#define CP_WAIT1()  asm volatile("cp.async.wait_group 1;")
#define CP_WAIT0()  asm volatile("cp.async.wait_group 0;")
__device__ __forceinline__ uint32_t smem_u32(const void* p) {
    uint32_t a;
    asm("{ .reg .u64 t; cvta.to.shared.u64 t, %1; cvt.u32.u64 %0, t; }" : "=r"(a) : "l"(p));
    return a;
}
__device__ __forceinline__ uint32_t h2u(__half2 h) { return *reinterpret_cast<uint32_t*>(&h); }

// ================= merged prep kernel =================
__global__ __launch_bounds__(256) void prep_all(
    const float* __restrict__ x, const float* __restrict__ w,
    const float* __restrict__ wo, const float* __restrict__ pe)
{
    const int blk = blockIdx.x;
    const int tid = threadIdx.x;
    if (blk < 9408) {
        int i = blk * 256 + tid;
        int e = i * 4;
        int t = e / 192, c = e - t * 192;
        int b = t / 3136; int r = t - b * 3136;
        int y = r / 56, xx = r - y * 56;
        int ys = y + 3;  if (ys >= 56) ys -= 56;
        int xs = xx + 3; if (xs >= 56) xs -= 56;
        float4 v = *(const float4*)(x + ((b * 56 + ys) * 56 + xs) * 192 + c);
        int gb = e & ~15;
        int q = (e >> 1) & 7;
        int p0 = ((q & 3) << 1) | (q >> 2);
        int q1 = q + 1;
        int p1 = ((q1 & 3) << 1) | (q1 >> 2);
        *(__half2*)(g_xh + gb + 2 * p0) = __floats2half2_rn(v.x, v.y);
        *(__half2*)(g_xh + gb + 2 * p1) = __floats2half2_rn(v.z, v.w);
    } else if (blk < 9552) {
        int i = (blk - 9408) * 256 + tid;
        int e = i * 4;
        __half* dst;
        float vv[4];
        if (e < 110592) {
            int n = e / 192, k = e - n * 192;
#pragma unroll
            for (int j = 0; j < 4; j++) vv[j] = w[(k + j) * 576 + n];
            dst = g_wh;
        } else {
            int e2 = e - 110592;
            int n = e2 / 192, k = e2 - n * 192;
#pragma unroll
            for (int j = 0; j < 4; j++) vv[j] = wo[(k + j) * 192 + n];
            dst = g_woh - 110592;
        }
        int gb = e & ~15;
        int q = (e >> 1) & 7;
        int p0 = ((q & 3) << 1) | (q >> 2);
        int q1 = q + 1;
        int p1 = ((q1 & 3) << 1) | (q1 >> 2);
        *(__half2*)(dst + gb + 2 * p0) = __floats2half2_rn(vv[0], vv[1]);
        *(__half2*)(dst + gb + 2 * p1) = __floats2half2_rn(vv[2], vv[3]);
    } else {
        int idx = (blk - 9552) * 256 + tid;
        int type = idx >> 12, r = idx & 4095;
        int i = r >> 6, j = r & 63;
        float v = -1e9f;
        if (i < 49 && j < 49) {
            int iy = i / 7, ix = i - iy * 7;
            int jy = j / 7, jx = j - jy * 7;
            v = pe[(jy - iy + 6) * 13 + (jx - ix + 6)];
            if ((type & 2) && ((iy >= 4) != (jy >= 4))) v -= 1e9f;
            if ((type & 1) && ((ix >= 4) != (jx >= 4))) v -= 1e9f;
        }
        g_bias[idx] = v;
    }
}

// ==== fp16 GEMM: BM=128, BN=96, BK=64, 128 threads (4 warps 2x2, warp 64x48) ====
// 3 chunks, 2-stage double buffer. LDA=80 halves (160B): bank step 8 -> conflict-free.
#define LDA 80
#define A_ST (128 * LDA)
#define B_ST (96 * LDA)
#define STAGE (A_ST + B_ST)
#define GSMEM (2 * STAGE * 2)        // 71680 B dynamic

// ================= Kernel 1: QKV GEMM =================
__global__ __launch_bounds__(128, 3) void qkv_gemm(void)
{
    extern __shared__ __align__(16) __half sm[];

    const int tid  = threadIdx.x;
    const int warp = tid >> 5, lane = tid & 31;
    const int wm   = warp & 1, wn = warp >> 1;
    const int g    = lane >> 2, tg = lane & 3;
    const int bm   = blockIdx.x * 128;
    const int nb   = blockIdx.y;

    const __half* ap = g_xh + (size_t)(bm + tid) * 192;       // row per thread
    const uint32_t smb = smem_u32(sm);

#define LD_CHUNK(cc, ss) do { \
        uint32_t ad = smb + (uint32_t)((ss) * STAGE + tid * LDA) * 2; \
        const __half* asrc = ap + (cc) * 64; \
        cpa16(ad + 0,  asrc + 0);  cpa16(ad + 16, asrc + 8); \
        cpa16(ad + 32, asrc + 16); cpa16(ad + 48, asrc + 24); \
        cpa16(ad + 64, asrc + 32); cpa16(ad + 80, asrc + 40); \
        cpa16(ad + 96, asrc + 48); cpa16(ad + 112, asrc + 56); \
        uint32_t bd = smb + (uint32_t)((ss) * STAGE + A_ST) * 2; \
        _Pragma("unroll") \
        for (int ii = 0; ii < 6; ii++) { \
            int e = tid + ii * 128; int n = e >> 3, c16 = e & 7; \
            cpa16(bd + (uint32_t)(n * LDA + c16 * 8) * 2, \
                  g_wh + (size_t)(nb * 96 + n) * 192 + (cc) * 64 + c16 * 8); \
        } \
        CP_COMMIT(); } while (0)

    float c[4][6][4] = {};
    LD_CHUNK(0, 0);

#pragma unroll 1
    for (int ch = 0; ch < 3; ch++) {
        const int st = ch & 1;
        __syncthreads();                 // prior compute on stage st^1 finished
        if (ch < 2) { LD_CHUNK(ch + 1, st ^ 1); CP_WAIT1(); }
        else        { CP_WAIT0(); }
        __syncthreads();

        const __half* Ab = sm + st * STAGE;
        const __half* Bb = Ab + A_ST;
#pragma unroll
        for (int kk = 0; kk < 64; kk += 16) {
            uint32_t af[4][4], bf[6][2];
#pragma unroll
            for (int mi = 0; mi < 4; mi++) {
                const int rb = wm * 64 + mi * 16 + g;
                uint2 v0 = *(const uint2*)(Ab + rb * LDA + kk + 4 * tg);
                uint2 v1 = *(const uint2*)(Ab + (rb + 8) * LDA + kk + 4 * tg);
                af[mi][0] = v0.x; af[mi][2] = v0.y;
                af[mi][1] = v1.x; af[mi][3] = v1.y;
            }
#pragma unroll
            for (int ni = 0; ni < 6; ni++) {
                uint2 vb = *(const uint2*)(Bb + (wn * 48 + ni * 8 + g) * LDA + kk + 4 * tg);
                bf[ni][0] = vb.x; bf[ni][1] = vb.y;
            }
#pragma unroll
            for (int mi = 0; mi < 4; mi++)
#pragma unroll
                for (int ni = 0; ni < 6; ni++)
                    mma16(c[mi][ni], af[mi], bf[ni]);
        }
    }

    // epilogue: scatter into window layout; q pre-scaled by 1/sqrt(32)
    const int t = nb >> 1;
    const float smul = (t == 0) ? 0.17677669529663687f : 1.0f;
    __half* qb = g_qkvh + (size_t)t * QT;
#pragma unroll
    for (int mi = 0; mi < 4; mi++) {
#pragma unroll
        for (int half = 0; half < 2; half++) {
            int r = bm + wm * 64 + mi * 16 + g + half * 8;
            int b = r / 3136; int rr = r - b * 3136;
            int y = rr / 56, xx = rr - y * 56;
            int wv = (y / 7) * 8 + (xx / 7);
            int tk = (y % 7) * 7 + (xx % 7);
            __half* base = qb + b * 602112 + wv * 1568 + tk * 32;
#pragma unroll
            for (int ni = 0; ni < 6; ni++) {
                int cp = nb * 96 + wn * 48 + ni * 8 + tg * 2;
                int cc = cp - t * 192;
                int h = cc >> 5, d = cc & 31;
                *(__half2*)(base + h * 100352 + d) =
                    __floats2half2_rn(c[mi][ni][half * 2] * smul,
                                      c[mi][ni][half * 2 + 1] * smul);
            }
        }
    }
}

// ================= Kernel 2: HMMA attention (cp.async loads, padded cols skipped) =================
#define LDQ 40

__global__ __launch_bounds__(128) void attn_hmma(void)
{
    __shared__ __align__(16) __half Qs[64 * LDQ];
    __shared__ __align__(16) __half Ks[64 * LDQ];
    __shared__ __align__(16) __half Vs[64 * LDQ];

    const int tid = threadIdx.x;
    const int w = tid >> 5, lane = tid & 31;
    const int g = lane >> 2, t = lane & 3;
    const int bx = blockIdx.x;
    const int wv = bx & 63;
    const int wtype = ((wv >> 3) == 7 ? 2 : 0) | ((wv & 7) == 7 ? 1 : 0);
    const float* bias = g_bias + wtype * 4096;

    const uint32_t qs_b = smem_u32(Qs), ks_b = smem_u32(Ks), vs_b = smem_u32(Vs);

    // cp.async loads: 3 tensors x 49 rows x 4 x 16B = 588 transfers
    {
        const __half* gq = g_qkvh + (size_t)bx * 1568;
#pragma unroll
        for (int ii = 0; ii < 5; ii++) {
            int e = tid + ii * 128;
            if (e < 588) {
                int tn = e / 196; int rem = e - tn * 196;
                int row = rem >> 2, c16 = rem & 3;
                uint32_t dstb = (tn == 0) ? qs_b : (tn == 1) ? ks_b : vs_b;
                cpa16(dstb + (uint32_t)(row * LDQ + c16 * 8) * 2,
                      gq + (size_t)tn * QT + row * 32 + c16 * 8);
            }
        }
        CP_COMMIT();
    }
    // zero pad rows 49..63 (16 used words per row; zero all 20)
    for (int p = tid; p < 900; p += 128) {
        int tn = p / 300; int r2 = p - tn * 300;
        int row = 49 + r2 / 20, wd = r2 % 20;
        uint32_t dstb = (tn == 0) ? qs_b : (tn == 1) ? ks_b : vs_b;
        *(uint32_t*)((char*)Qs + (dstb - qs_b) + (uint32_t)(row * LDQ + wd * 2) * 2) = 0u;
    }
    CP_WAIT0();
    __syncthreads();

    // ---- S = (Q*scale) K^T ; skip padded n=7 ----
    float S[8][4] = {};
    const __half* qrow = Qs + (w * 16 + g) * LDQ;
#pragma unroll
    for (int kk = 0; kk < 32; kk += 16) {
        uint32_t a[4];
        a[0] = *(const uint32_t*)(qrow + kk + 2 * t);
        a[1] = *(const uint32_t*)(qrow + 8 * LDQ + kk + 2 * t);
        a[2] = *(const uint32_t*)(qrow + kk + 8 + 2 * t);
        a[3] = *(const uint32_t*)(qrow + 8 * LDQ + kk + 8 + 2 * t);
#pragma unroll
        for (int n = 0; n < 7; n++) {
            uint32_t b[2];
            const __half* kb = Ks + (n * 8 + g) * LDQ + kk + 2 * t;
            b[0] = *(const uint32_t*)(kb);
            b[1] = *(const uint32_t*)(kb + 8);
            mma16(S[n], a, b);
        }
    }

    // ---- bias + softmax; real j only (j<49). n=6 has one real elem (t==0,e==0). ----
#pragma unroll
    for (int rw = 0; rw < 2; rw++) {
        int i = w * 16 + g + rw * 8;
        const float* brow = bias + i * 64 + 2 * t;
        float mx = -1e30f;
#pragma unroll
        for (int n = 0; n < 6; n++) {
            float2 bb = *(const float2*)(brow + n * 8);
            float v0 = S[n][rw * 2]     + bb.x;
            float v1 = S[n][rw * 2 + 1] + bb.y;
            S[n][rw * 2]     = v0;
            S[n][rw * 2 + 1] = v1;
            mx = fmaxf(mx, fmaxf(v0, v1));
        }
        float v6 = -1e30f;
        if (t == 0) {
            v6 = S[6][rw * 2] + brow[48];   // j = 48
            mx = fmaxf(mx, v6);
        }
        mx = fmaxf(mx, __shfl_xor_sync(0xffffffffu, mx, 1));
        mx = fmaxf(mx, __shfl_xor_sync(0xffffffffu, mx, 2));
        float sm = 0.f;
#pragma unroll
        for (int n = 0; n < 6; n++) {
#pragma unroll
            for (int e = 0; e < 2; e++) {
                float ex = __expf(S[n][rw * 2 + e] - mx);
                S[n][rw * 2 + e] = ex;
                sm += ex;
            }
        }
        if (t == 0) {
            float e6 = __expf(v6 - mx);
            S[6][rw * 2] = e6;
            sm += e6;
        } else {
            S[6][rw * 2] = 0.f;
        }
        S[6][rw * 2 + 1] = 0.f;
        S[7][rw * 2] = 0.f;
        S[7][rw * 2 + 1] = 0.f;
        sm += __shfl_xor_sync(0xffffffffu, sm, 1);
        sm += __shfl_xor_sync(0xffffffffu, sm, 2);
        float inv = 1.f / sm;
#pragma unroll
        for (int n = 0; n < 6; n++) {
            S[n][rw * 2 + 0] *= inv;
            S[n][rw * 2 + 1] *= inv;
        }
        S[6][rw * 2] *= inv;
    }

    // ---- repack P into A-fragments ----
    uint32_t Pa[4][4];
#pragma unroll
    for (int c = 0; c < 4; c++) {
        Pa[c][0] = h2u(__floats2half2_rn(S[2 * c][0],     S[2 * c][1]));
        Pa[c][1] = h2u(__floats2half2_rn(S[2 * c][2],     S[2 * c][3]));
        Pa[c][2] = h2u(__floats2half2_rn(S[2 * c + 1][0], S[2 * c + 1][1]));
        Pa[c][3] = h2u(__floats2half2_rn(S[2 * c + 1][2], S[2 * c + 1][3]));
    }

    // ---- O = P V  (B-fragments via ldmatrix.trans on natural V) ----
    const int lr = lane & 7, lm = (lane >> 3) & 1, lk = lane >> 4;
    float O[4][4] = {};
#pragma unroll
    for (int c = 0; c < 4; c++) {
#pragma unroll
        for (int nh = 0; nh < 2; nh++) {
            uint32_t r[4];
            ldsm4t(r, vs_b + (uint32_t)((c * 16 + lr + lm * 8) * LDQ + nh * 16 + lk * 8) * 2);
            uint32_t b0[2] = { r[0], r[1] };
            uint32_t b1[2] = { r[2], r[3] };
            mma16(O[nh * 2],     Pa[c], b0);
            mma16(O[nh * 2 + 1], Pa[c], b1);
        }
    }

    // ---- store fp16, permuted-k layout ----
    __half* og = g_atth + (size_t)bx * 1568;
#pragma unroll
    for (int rw = 0; rw < 2; rw++) {
        int i = w * 16 + g + rw * 8;
        if (i < 49) {
#pragma unroll
            for (int nt = 0; nt < 4; nt++) {
                int h = nt * 8 + 2 * t;
                int b16 = h & 16;
                int q = (h >> 1) & 7;
                int pp = ((q & 3) << 1) | (q >> 2);
                *(__half2*)(og + i * 32 + b16 + 2 * pp) =
                    __floats2half2_rn(O[nt][rw * 2], O[nt][rw * 2 + 1]);
            }
        }
    }
}

// ================= Kernel 3: out-proj GEMM + inverse roll (BK=64, 2-stage) =================
__global__ __launch_bounds__(128, 3) void proj_gemm(
    const float* __restrict__ bout, float* __restrict__ out)
{
    extern __shared__ __align__(16) __half sm[];

    const int tid  = threadIdx.x;
    const int warp = tid >> 5, lane = tid & 31;
    const int wm   = warp & 1, wn = warp >> 1;
    const int g    = lane >> 2, tg = lane & 3;
    const int bm   = blockIdx.x * 128;
    const int nb   = blockIdx.y;

    const __half* abase;
    {
        int row = bm + tid;
        int b = row / 3136; int r = row - b * 3136;
        int y = r / 56, xx = r - y * 56;
        int wv = (y / 7) * 8 + (xx / 7);
        int tk = (y % 7) * 7 + (xx % 7);
        abase = g_atth + b * 602112 + wv * 1568 + tk * 32;   // + h*100352 + d
    }
    const uint32_t smb = smem_u32(sm);

    // A chunk cc covers heads 2cc, 2cc+1 (32 halves each)
#define LD_CHUNK_P(cc, ss) do { \
        uint32_t ad = smb + (uint32_t)((ss) * STAGE + tid * LDA) * 2; \
        const __half* a0 = abase + (2 * (cc)) * 100352; \
        const __half* a1 = abase + (2 * (cc) + 1) * 100352; \
        cpa16(ad + 0,  a0 + 0);  cpa16(ad + 16, a0 + 8); \
        cpa16(ad + 32, a0 + 16); cpa16(ad + 48, a0 + 24); \
        cpa16(ad + 64, a1 + 0);  cpa16(ad + 80, a1 + 8); \
        cpa16(ad + 96, a1 + 16); cpa16(ad + 112, a1 + 24); \
        uint32_t bd = smb + (uint32_t)((ss) * STAGE + A_ST) * 2; \
        _Pragma("unroll") \
        for (int ii = 0; ii < 6; ii++) { \
            int e = tid + ii * 128; int n = e >> 3, c16 = e & 7; \
            cpa16(bd + (uint32_t)(n * LDA + c16 * 8) * 2, \
                  g_woh + (size_t)(nb * 96 + n) * 192 + (cc) * 64 + c16 * 8); \
        } \
        CP_COMMIT(); } while (0)

    float c[4][6][4] = {};
    LD_CHUNK_P(0, 0);

#pragma unroll 1
    for (int ch = 0; ch < 3; ch++) {
        const int st = ch & 1;
        __syncthreads();
        if (ch < 2) { LD_CHUNK_P(ch + 1, st ^ 1); CP_WAIT1(); }
        else        { CP_WAIT0(); }
        __syncthreads();

        const __half* Ab = sm + st * STAGE;
        const __half* Bb = Ab + A_ST;
#pragma unroll
        for (int kk = 0; kk < 64; kk += 16) {
            uint32_t af[4][4], bf[6][2];
#pragma unroll
            for (int mi = 0; mi < 4; mi++) {
                const int rb = wm * 64 + mi * 16 + g;
                uint2 v0 = *(const uint2*)(Ab + rb * LDA + kk + 4 * tg);
                uint2 v1 = *(const uint2*)(Ab + (rb + 8) * LDA + kk + 4 * tg);
                af[mi][0] = v0.x; af[mi][2] = v0.y;
                af[mi][1] = v1.x; af[mi][3] = v1.y;
            }
#pragma unroll
            for (int ni = 0; ni < 6; ni++) {
                uint2 vb = *(const uint2*)(Bb + (wn * 48 + ni * 8 + g) * LDA + kk + 4 * tg);
                bf[ni][0] = vb.x; bf[ni][1] = vb.y;
            }
#pragma unroll
            for (int mi = 0; mi < 4; mi++)
#pragma unroll
                for (int ni = 0; ni < 6; ni++)
                    mma16(c[mi][ni], af[mi], bf[ni]);
        }
    }

#pragma unroll
    for (int mi = 0; mi < 4; mi++) {
#pragma unroll
        for (int half = 0; half < 2; half++) {
            int r = bm + wm * 64 + mi * 16 + g + half * 8;
            int b = r / 3136; int rr = r - b * 3136;
            int y = rr / 56, xx = rr - y * 56;
            int yo = y + 3;  if (yo >= 56) yo -= 56;
            int xo = xx + 3; if (xo >= 56) xo -= 56;
            float* op = out + ((b * 56 + yo) * 56 + xo) * 192;
#pragma unroll
            for (int ni = 0; ni < 6; ni++) {
                int cp = nb * 96 + wn * 48 + ni * 8 + tg * 2;
                float2 bb = *(const float2*)(bout + cp);
                float2 v = make_float2(c[mi][ni][half * 2] + bb.x,
                                       c[mi][ni][half * 2 + 1] + bb.y);
                *(float2*)(op + cp) = v;
            }
        }
    }
}

// ================= launch =================
extern "C" void kernel_launch(void* const* d_in, const int* in_sizes, int n_in,
                              void* d_out, int out_size)
{
    const float* x    = (const float*)d_in[0];
    const float* wqkv = (const float*)d_in[1];
    const float* pe   = (const float*)d_in[2];
    const float* wout = (const float*)d_in[3];
    const float* bout = (const float*)d_in[4];
    float* out = (float*)d_out;

    static int configured = 0;
    if (!configured) {
        cudaFuncSetAttribute(qkv_gemm, cudaFuncAttributeMaxDynamicSharedMemorySize, GSMEM);
        cudaFuncSetAttribute(proj_gemm, cudaFuncAttributeMaxDynamicSharedMemorySize, GSMEM);
        configured = 1;
    }

    prep_all<<<9616, 256>>>(x, wqkv, wout, pe);

    dim3 g1(392, 6);
    qkv_gemm<<<g1, 128, GSMEM>>>();

    attn_hmma<<<16 * 6 * 64, 128>>>();

    dim3 g3(392, 2);
    proj_gemm<<<g3, 128, GSMEM>>>(bout, out);
}